// round 2
// baseline (speedup 1.0000x reference)
#include <cuda_runtime.h>
#include <math.h>

#define SB 200   // encoder sequence length
#define TB 200   // decoder sequence length
#define BB 256   // batch
#define HH 512   // hidden
#define VV 512   // vocab
#define NB 128   // persistent blocks (<= #SMs, all co-resident)

// ---------------- device scratch (no allocations allowed) ----------------
__device__ float g_xs[SB * BB * HH];     // encoder input embeddings (S,B,H)
__device__ float g_de[TB * BB * HH];     // decoder input embeddings (T,B,H)
__device__ float g_eo[SB * BB * HH];     // encoder outputs (S,B,H)
__device__ float g_h[2][BB * HH];        // hidden ping-pong
__device__ float g_ah[BB * HH];          // relu(h @ att_W^T + att_b)
__device__ float g_ctx[BB * HH];         // attention context
__device__ float g_xv[BB * HH];          // decoder GRU input x
__device__ float g_logits[BB * VV];      // output logits
__device__ float g_loss_tb[TB * BB];     // per-(t,b) -log p

// ---------------- software grid barrier (sense-reversal by generation) ----
__device__ unsigned g_cnt = 0;
__device__ volatile unsigned g_gen = 0;

__device__ __forceinline__ void gsync() {
    __syncthreads();
    if (threadIdx.x == 0) {
        __threadfence();                       // release my writes
        unsigned gen = g_gen;
        if (atomicAdd(&g_cnt, 1u) == NB - 1) {
            g_cnt = 0;
            __threadfence();
            g_gen = gen + 1;                   // release
        } else {
            while (g_gen == gen) { }           // spin on L2
        }
        __threadfence();                       // acquire others' writes
    }
    __syncthreads();
}

// shared scratch: max(gru 17408, gemm 8704, attn 18496, out 2048)
#define SMEM_BYTES 18560

// ---------------- fused GRU step (32x32 tile, all 3 gates) ----------------
template <bool ENC>
__device__ __forceinline__ void gru_phase(
    int step,
    const float* __restrict__ X, const float* __restrict__ Hin,
    float* __restrict__ Hout, float* __restrict__ eout,
    const float* __restrict__ Wih, const float* __restrict__ Whh,
    const float* __restrict__ bih, const float* __restrict__ bhh,
    const int* __restrict__ ilen, char* raw) {

    float (*As)[34]     = (float (*)[34])raw;
    float (*Ws)[32][34] = (float (*)[32][34])(raw + 32 * 34 * 4);

    const int tid = threadIdx.x;
    const int tx = tid & 15, ty = tid >> 4;
    const int bB = (blockIdx.x & 7) * 32, jB = (blockIdx.x >> 3) * 32;
    const int lk = tid & 31, lr = tid >> 5;

    float ar[2][2]  = {{0.f, 0.f}, {0.f, 0.f}};
    float az[2][2]  = {{0.f, 0.f}, {0.f, 0.f}};
    float ani[2][2] = {{0.f, 0.f}, {0.f, 0.f}};
    float anh[2][2] = {{0.f, 0.f}, {0.f, 0.f}};

    for (int phase = 0; phase < 2; phase++) {
        const float* A  = phase ? Hin : X;
        const float* Wm = phase ? Whh : Wih;
        for (int kc = 0; kc < HH; kc += 32) {
            __syncthreads();
#pragma unroll
            for (int i = 0; i < 4; i++)
                As[lk][lr + i * 8] = A[(bB + lr + i * 8) * HH + kc + lk];
#pragma unroll
            for (int g = 0; g < 3; g++)
#pragma unroll
                for (int i = 0; i < 4; i++)
                    Ws[g][lk][lr + i * 8] =
                        Wm[(g * HH + jB + lr + i * 8) * HH + kc + lk];
            __syncthreads();
#pragma unroll
            for (int kk = 0; kk < 32; kk++) {
                float2 a  = *(const float2*)&As[kk][ty * 2];
                float2 w0 = *(const float2*)&Ws[0][kk][tx * 2];
                float2 w1 = *(const float2*)&Ws[1][kk][tx * 2];
                float2 w2 = *(const float2*)&Ws[2][kk][tx * 2];
                ar[0][0] += a.x * w0.x; ar[0][1] += a.x * w0.y;
                ar[1][0] += a.y * w0.x; ar[1][1] += a.y * w0.y;
                az[0][0] += a.x * w1.x; az[0][1] += a.x * w1.y;
                az[1][0] += a.y * w1.x; az[1][1] += a.y * w1.y;
                if (phase == 0) {
                    ani[0][0] += a.x * w2.x; ani[0][1] += a.x * w2.y;
                    ani[1][0] += a.y * w2.x; ani[1][1] += a.y * w2.y;
                } else {
                    anh[0][0] += a.x * w2.x; anh[0][1] += a.x * w2.y;
                    anh[1][0] += a.y * w2.x; anh[1][1] += a.y * w2.y;
                }
            }
        }
    }

#pragma unroll
    for (int bi = 0; bi < 2; bi++) {
        int b = bB + ty * 2 + bi;
#pragma unroll
        for (int ji = 0; ji < 2; ji++) {
            int j = jB + tx * 2 + ji;
            float r = 1.f / (1.f + expf(-(ar[bi][ji] + bih[j] + bhh[j])));
            float z = 1.f / (1.f + expf(-(az[bi][ji] + bih[HH + j] + bhh[HH + j])));
            float n = tanhf(ani[bi][ji] + bih[2 * HH + j] +
                            r * (anh[bi][ji] + bhh[2 * HH + j]));
            float hp   = Hin[b * HH + j];
            float hnew = (1.f - z) * n + z * hp;
            if (ENC) {
                bool m   = step < ilen[b];
                float ho = m ? hnew : hp;
                Hout[b * HH + j] = ho;
                eout[b * HH + j] = m ? ho : 0.f;
            } else {
                Hout[b * HH + j] = hnew;
            }
        }
    }
    __syncthreads();
}

// ---------------- generic tiled GEMM + fused bias/activation ----------------
// mode 0: out = relu(A1 @ W^T + b)   K=512
// mode 1: out = tanh([A1|A2] @ W^T + b)  K=1024
// mode 2: out = A1 @ W^T + b         K=512
__device__ __forceinline__ void gemm_phase(
    int mode, const float* __restrict__ A1, const float* __restrict__ A2,
    const float* __restrict__ W, const float* __restrict__ bias,
    float* __restrict__ out, char* raw) {

    float (*As)[34] = (float (*)[34])raw;
    float (*Bs)[34] = (float (*)[34])(raw + 32 * 34 * 4);
    const int Ktot = (mode == 1) ? 2 * HH : HH;

    const int tid = threadIdx.x;
    const int tx = tid & 15, ty = tid >> 4;
    const int bB = (blockIdx.x & 7) * 32, nB = (blockIdx.x >> 3) * 32;
    const int lk = tid & 31, lr = tid >> 5;
    float acc[2][2] = {{0.f, 0.f}, {0.f, 0.f}};

    for (int kc = 0; kc < Ktot; kc += 32) {
        __syncthreads();
        const float* A = (kc < HH) ? A1 : A2;
        int kloc = (kc < HH) ? kc : (kc - HH);
#pragma unroll
        for (int i = 0; i < 4; i++)
            As[lk][lr + i * 8] = A[(bB + lr + i * 8) * HH + kloc + lk];
#pragma unroll
        for (int i = 0; i < 4; i++)
            Bs[lk][lr + i * 8] = W[(size_t)(nB + lr + i * 8) * Ktot + kc + lk];
        __syncthreads();
#pragma unroll
        for (int kk = 0; kk < 32; kk++) {
            float2 a = *(const float2*)&As[kk][ty * 2];
            float2 w = *(const float2*)&Bs[kk][tx * 2];
            acc[0][0] += a.x * w.x; acc[0][1] += a.x * w.y;
            acc[1][0] += a.y * w.x; acc[1][1] += a.y * w.y;
        }
    }
#pragma unroll
    for (int bi = 0; bi < 2; bi++) {
        int b = bB + ty * 2 + bi;
#pragma unroll
        for (int ji = 0; ji < 2; ji++) {
            int n = nB + tx * 2 + ji;
            float c = acc[bi][ji] + bias[n];
            if (mode == 0)      c = fmaxf(c, 0.f);
            else if (mode == 1) c = tanhf(c);
            out[b * HH + n] = c;
        }
    }
    __syncthreads();
}

// ---------------- single-pass online-softmax attention for one batch row ----
__device__ __forceinline__ void attn_phase(int b, char* raw) {
    float* ah   = (float*)raw;           // 512
    float* wm   = ah + 512;              // 8
    float* wsum = wm + 8;                // 8
    float* wctx = wsum + 8;              // 8*512

    const int tid = threadIdx.x, warp = tid >> 5, lane = tid & 31;
    ah[tid]       = g_ah[b * HH + tid];
    ah[tid + 256] = g_ah[b * HH + tid + 256];
    __syncthreads();

    float ahr[16];
#pragma unroll
    for (int i = 0; i < 16; i++) ahr[i] = ah[lane + 32 * i];

    float m = -1e30f, s = 0.f;
    float ctx[16];
#pragma unroll
    for (int i = 0; i < 16; i++) ctx[i] = 0.f;

    for (int sI = warp; sI < SB; sI += 8) {              // 25 iters/warp, no tail
        const float* eo = g_eo + ((size_t)sI * BB + b) * HH;
        float ev[16], d = 0.f;
#pragma unroll
        for (int i = 0; i < 16; i++) { ev[i] = eo[lane + 32 * i]; d += ev[i] * ahr[i]; }
#pragma unroll
        for (int o = 16; o > 0; o >>= 1) d += __shfl_xor_sync(0xffffffffu, d, o);
        float mn = fmaxf(m, d);
        float sc = expf(m - mn);
        float p  = expf(d - mn);
        s = s * sc + p;
#pragma unroll
        for (int i = 0; i < 16; i++) ctx[i] = ctx[i] * sc + p * ev[i];
        m = mn;
    }
    if (lane == 0) { wm[warp] = m; wsum[warp] = s; }
#pragma unroll
    for (int i = 0; i < 16; i++) wctx[warp * 512 + lane + 32 * i] = ctx[i];
    __syncthreads();

    float M = -1e30f;
#pragma unroll
    for (int w = 0; w < 8; w++) M = fmaxf(M, wm[w]);
    float S = 0.f, esc[8];
#pragma unroll
    for (int w = 0; w < 8; w++) { esc[w] = expf(wm[w] - M); S += wsum[w] * esc[w]; }
    float inv = 1.f / S;
#pragma unroll
    for (int hh = 0; hh < 2; hh++) {
        int h = tid + hh * 256;
        float acc = 0.f;
#pragma unroll
        for (int w = 0; w < 8; w++) acc += esc[w] * wctx[w * 512 + h];
        g_ctx[b * HH + h] = acc * inv;
    }
    __syncthreads();
}

// ---------------- output softmax / argmax / per-(t,b) loss for one batch ----
__device__ __forceinline__ void out_phase(int t, int b, const int* __restrict__ tseq,
                                          float* __restrict__ dout, char* raw) {
    float* sv = (float*)raw;
    int*   si = (int*)(raw + 1024);
    const int tid = threadIdx.x;
    const float* lrow = g_logits + b * VV;
    float v0 = lrow[tid], v1 = lrow[tid + 256];
    float mv; int mi;
    if (v0 >= v1) { mv = v0; mi = tid; } else { mv = v1; mi = tid + 256; }
    sv[tid] = mv; si[tid] = mi;
    __syncthreads();
    for (int o = 128; o > 0; o >>= 1) {
        if (tid < o) {
            float ov = sv[tid + o]; int oi = si[tid + o];
            if (ov > sv[tid] || (ov == sv[tid] && oi < si[tid])) { sv[tid] = ov; si[tid] = oi; }
        }
        __syncthreads();
    }
    float bmax = sv[0];
    int pred = si[0];
    __syncthreads();
    sv[tid] = expf(v0 - bmax) + expf(v1 - bmax);
    __syncthreads();
    for (int o = 128; o > 0; o >>= 1) {
        if (tid < o) sv[tid] += sv[tid + o];
        __syncthreads();
    }
    if (tid == 0) {
        int tgt = tseq[t * BB + b];
        float p = expf(lrow[tgt] - bmax) / sv[0];
        p = fmaxf(p, 1e-10f);
        g_loss_tb[t * BB + b] = -logf(p);
        dout[t * BB + b] = (float)pred;
    }
    __syncthreads();
}

// ---------------- persistent mega-kernel: everything in one node ----------
__global__ void __launch_bounds__(256) k_mega(
    const int* __restrict__ iseq, const int* __restrict__ ilen,
    const int* __restrict__ tseq,
    const float* __restrict__ eemb,
    const float* __restrict__ eWih, const float* __restrict__ eWhh,
    const float* __restrict__ ebih, const float* __restrict__ ebhh,
    const float* __restrict__ attW, const float* __restrict__ attb,
    const float* __restrict__ demb,
    const float* __restrict__ dWih, const float* __restrict__ dWhh,
    const float* __restrict__ dbih, const float* __restrict__ dbhh,
    const float* __restrict__ mlpW, const float* __restrict__ mlpb,
    const float* __restrict__ outW, const float* __restrict__ outb,
    float* __restrict__ dout) {

    __shared__ __align__(16) char raw[SMEM_BYTES];
    const int bid = blockIdx.x, tid = threadIdx.x;

    // --- init h0 + embedding gathers ---
    for (int i = bid * 256 + tid; i < BB * HH; i += NB * 256) g_h[0][i] = 0.f;
    for (int idx = bid; idx < (SB + TB) * BB; idx += NB) {
        const float2* src; float2* dst;
        if (idx < SB * BB) {
            int tok = iseq[idx];
            dst = (float2*)(g_xs + (size_t)idx * HH);
            src = (const float2*)(eemb + (size_t)tok * HH);
        } else {
            int r = idx - SB * BB;
            int t = r / BB, b = r - t * BB;
            int tok = (t == 0) ? 1 : tseq[(t - 1) * BB + b];
            dst = (float2*)(g_de + (size_t)r * HH);
            src = (const float2*)(demb + (size_t)tok * HH);
        }
        dst[tid] = src[tid];
    }
    gsync();

    // --- encoder: 200 GRU steps ---
    for (int s = 0; s < SB; s++) {
        int pin = s & 1;
        gru_phase<true>(s, g_xs + (size_t)s * BB * HH, g_h[pin], g_h[pin ^ 1],
                        g_eo + (size_t)s * BB * HH,
                        eWih, eWhh, ebih, ebhh, ilen, raw);
        gsync();
    }

    // --- decoder: 200 steps, 5 barriers each ---
    for (int t = 0; t < TB; t++) {
        int pin = t & 1;
        gemm_phase(0, g_h[pin], nullptr, attW, attb, g_ah, raw);       // ah
        gsync();
        attn_phase(bid * 2 + 0, raw);                                  // ctx
        attn_phase(bid * 2 + 1, raw);
        gsync();
        gemm_phase(1, g_de + (size_t)t * BB * HH, g_ctx, mlpW, mlpb,
                   g_xv, raw);                                         // x
        gsync();
        gru_phase<false>(t, g_xv, g_h[pin], g_h[pin ^ 1], nullptr,
                         dWih, dWhh, dbih, dbhh, nullptr, raw);
        gsync();
        gemm_phase(2, g_h[pin ^ 1], nullptr, outW, outb, g_logits, raw); // logits
        gsync();
        out_phase(t, bid * 2 + 0, tseq, dout, raw);                    // softmax/argmax
        out_phase(t, bid * 2 + 1, tseq, dout, raw);
        // no barrier: next phases touch disjoint buffers until the next gsync
    }
    gsync();

    // --- final deterministic reductions (block 0 only) ---
    if (bid != 0) return;
    {
        float* sf = (float*)raw;
        int*   sc = (int*)(raw + 1024);
        int*   sa = (int*)(raw + 2048);
        float ls = 0.f; int corr = 0;
        for (int i = tid; i < TB * BB; i += 256) {
            ls += g_loss_tb[i];
            corr += (dout[i] == (float)tseq[i]) ? 1 : 0;
        }
        int allc = 1;
        for (int t = 0; t < TB; t++)
            if (dout[t * BB + tid] != (float)tseq[t * BB + tid]) { allc = 0; break; }
        sf[tid] = ls; sc[tid] = corr; sa[tid] = allc;
        __syncthreads();
        for (int o = 128; o > 0; o >>= 1) {
            if (tid < o) { sf[tid] += sf[tid + o]; sc[tid] += sc[tid + o]; sa[tid] += sa[tid + o]; }
            __syncthreads();
        }
        if (tid == 0) {
            dout[TB * BB]     = sf[0] / (float)(TB * BB);        // loss
            dout[TB * BB + 1] = (float)sa[0] / (float)BB;        // acc
            dout[TB * BB + 2] = (float)sc[0] / (float)(TB * BB); // all_acc
        }
    }
}

// ---------------- host ----------------
extern "C" void kernel_launch(void* const* d_in, const int* in_sizes, int n_in,
                              void* d_out, int out_size) {
    (void)in_sizes; (void)n_in; (void)out_size;
    k_mega<<<NB, 256>>>(
        (const int*)d_in[0], (const int*)d_in[1], (const int*)d_in[2],
        (const float*)d_in[3], (const float*)d_in[4], (const float*)d_in[5],
        (const float*)d_in[6], (const float*)d_in[7], (const float*)d_in[8],
        (const float*)d_in[9], (const float*)d_in[10], (const float*)d_in[11],
        (const float*)d_in[12], (const float*)d_in[13], (const float*)d_in[14],
        (const float*)d_in[15], (const float*)d_in[16], (const float*)d_in[17],
        (const float*)d_in[18], (float*)d_out);
}

// round 4
// speedup vs baseline: 1.1746x; 1.1746x over previous
#include <cuda_runtime.h>
#include <math.h>

#define SB 200
#define TB 200
#define BB 256
#define HH 512
#define VV 512
#define NB 128    // persistent blocks, all co-resident
#define NT 256

// ---------------- device scratch ----------------
__device__ float g_eo[SB * BB * HH];      // encoder outputs (S,B,H)
__device__ float g_qpre[TB * BB * HH];    // de @ mlpW[:, :512]^T (exact round-2 order)
__device__ float g_h[2][BB * HH];         // hidden ping-pong
__device__ float g_xv[BB * HH];           // decoder GRU input x
__device__ float g_ctx[BB * HH];          // attention context
__device__ float g_ah[BB * HH];           // relu(h @ att_W^T + att_b)
__device__ float g_logits[BB * VV];       // logits (bias included)
__device__ float g_loss_tb[TB * BB];

// ---------------- grid barrier ----------------
__device__ unsigned g_cnt = 0;
__device__ volatile unsigned g_gen = 0;

__device__ __forceinline__ void gsync() {
    __syncthreads();
    if (threadIdx.x == 0) {
        __threadfence();
        unsigned gen = g_gen;
        if (atomicAdd(&g_cnt, 1u) == NB - 1) {
            g_cnt = 0;
            __threadfence();
            g_gen = gen + 1;
        } else {
            while (g_gen == gen) { }
        }
        __threadfence();
    }
    __syncthreads();
}

#define SMEM_BYTES 43264

#define FMA2(acc, a, b) \
    asm("fma.rn.f32x2 %0, %1, %2, %0;" : "+l"(acc) : "l"(a), "l"(b))

__device__ __forceinline__ float2 u2f2(unsigned long long v) {
    float2 r;
    asm("mov.b64 {%0, %1}, %2;" : "=f"(r.x), "=f"(r.y) : "l"(v));
    return r;
}

// ---------------- GRU step: 32b x 32j tiles, 3 gates, inline epilogue -------
// Bitwise-identical accumulation to round 2: per (b,j,gate) the fma chain is
// phase0 (X@Wih) k=0..511 ascending, then phase1 (H@Whh) k=0..511 ascending,
// with ar/az merged across phases, ani phase0-only, anh phase1-only.
template <bool ENC>
__device__ void gru_step(
    int s, const int* __restrict__ iseq, const float* __restrict__ eemb,
    const float* __restrict__ Xv,
    const float* __restrict__ Hin, float* __restrict__ Hout,
    float* __restrict__ eout,
    const float* __restrict__ Wih, const float* __restrict__ Whh,
    const float* __restrict__ bih, const float* __restrict__ bhh,
    const int* __restrict__ ilen, char* raw) {

    float (*As2)[32][66]    = (float (*)[32][66])raw;              // 16896 B
    float (*Ws)[3][32][34]  = (float (*)[3][32][34])(raw + 16896); // 26112 B
    int* tokS               = (int*)(raw + 43008);                 // 128 B

    const int tid = threadIdx.x;
    const int lk = tid & 31, lr = tid >> 5;
    const int tx = tid & 15, ty = tid >> 4;
    const int bB = (blockIdx.x & 7) * 32, jB = (blockIdx.x >> 3) * 32;

    if (ENC) {
        if (tid < 32) tokS[tid] = iseq[s * BB + bB + tid];
    }
    __syncthreads();

    unsigned long long ar2[2]  = {0ull, 0ull};
    unsigned long long az2[2]  = {0ull, 0ull};
    unsigned long long ani2[2] = {0ull, 0ull};
    unsigned long long anh2[2] = {0ull, 0ull};

    float av[4], wv[12];

    auto ldA = [&](int ph, int kc) {
        if (ph == 0) {
            if (ENC) {
#pragma unroll
                for (int i = 0; i < 4; i++)
                    av[i] = eemb[(size_t)tokS[lr + 8 * i] * HH + kc + lk];
            } else {
#pragma unroll
                for (int i = 0; i < 4; i++)
                    av[i] = Xv[(size_t)(bB + lr + 8 * i) * HH + kc + lk];
            }
        } else {
#pragma unroll
            for (int i = 0; i < 4; i++)
                av[i] = Hin[(size_t)(bB + lr + 8 * i) * HH + kc + lk];
        }
    };
    auto ldW = [&](int ph, int kc) {
        const float* Wm = ph ? Whh : Wih;
#pragma unroll
        for (int g = 0; g < 3; g++)
#pragma unroll
            for (int i = 0; i < 4; i++)
                wv[g * 4 + i] =
                    Wm[(size_t)(g * HH + jB + lr + 8 * i) * HH + kc + lk];
    };
    auto stb = [&](int buf) {
#pragma unroll
        for (int i = 0; i < 4; i++)
            *(float2*)&As2[buf][lk][2 * (lr + 8 * i)] = make_float2(av[i], av[i]);
#pragma unroll
        for (int g = 0; g < 3; g++)
#pragma unroll
            for (int i = 0; i < 4; i++)
                Ws[buf][g][lk][lr + 8 * i] = wv[g * 4 + i];
    };

#define GRU_INNER(AN)                                                          \
    _Pragma("unroll")                                                          \
    for (int kk = 0; kk < 32; kk++) {                                          \
        unsigned long long a0 =                                                \
            *(const unsigned long long*)&As2[buf][kk][ty * 4];                 \
        unsigned long long a1 =                                                \
            *(const unsigned long long*)&As2[buf][kk][ty * 4 + 2];             \
        unsigned long long w0 =                                                \
            *(const unsigned long long*)&Ws[buf][0][kk][tx * 2];               \
        unsigned long long w1 =                                                \
            *(const unsigned long long*)&Ws[buf][1][kk][tx * 2];               \
        unsigned long long w2 =                                                \
            *(const unsigned long long*)&Ws[buf][2][kk][tx * 2];               \
        FMA2(ar2[0], a0, w0); FMA2(ar2[1], a1, w0);                            \
        FMA2(az2[0], a0, w1); FMA2(az2[1], a1, w1);                            \
        FMA2(AN[0],  a0, w2); FMA2(AN[1],  a1, w2);                            \
    }

    ldA(0, 0); ldW(0, 0); stb(0);
    __syncthreads();
    for (int c = 0; c < 32; c++) {
        const int buf = c & 1;
        if (c < 31) { int nc = c + 1; ldA(nc >> 4, (nc & 15) << 5); ldW(nc >> 4, (nc & 15) << 5); }
        if (c < 16) { GRU_INNER(ani2) } else { GRU_INNER(anh2) }
        if (c < 31) stb(buf ^ 1);
        __syncthreads();
    }
#undef GRU_INNER

    float2 arf[2] = {u2f2(ar2[0]), u2f2(ar2[1])};
    float2 azf[2] = {u2f2(az2[0]), u2f2(az2[1])};
    float2 anif[2] = {u2f2(ani2[0]), u2f2(ani2[1])};
    float2 anhf[2] = {u2f2(anh2[0]), u2f2(anh2[1])};

#pragma unroll
    for (int r = 0; r < 2; r++) {
        int b = bB + ty * 2 + r;
#pragma unroll
        for (int l = 0; l < 2; l++) {
            int j = jB + tx * 2 + l;
            float ar  = l ? arf[r].y  : arf[r].x;
            float az  = l ? azf[r].y  : azf[r].x;
            float ani = l ? anif[r].y : anif[r].x;
            float anh = l ? anhf[r].y : anhf[r].x;
            float rr = 1.f / (1.f + expf(-(ar + bih[j] + bhh[j])));
            float zz = 1.f / (1.f + expf(-(az + bih[HH + j] + bhh[HH + j])));
            float nn = tanhf(ani + bih[2 * HH + j] + rr * (anh + bhh[2 * HH + j]));
            float hp = Hin[b * HH + j];
            float hnew = (1.f - zz) * nn + zz * hp;
            if (ENC) {
                bool m = s < ilen[b];
                float ho = m ? hnew : hp;
                Hout[b * HH + j] = ho;
                eout[b * HH + j] = m ? ho : 0.f;
            } else {
                Hout[b * HH + j] = hnew;
            }
        }
    }
}

// ---------------- 32b x (32*JW)n GEMM core, K=512, double-buffered ----------
template <int JW>
__device__ __forceinline__ void gemm_core(
    const float* const* pA, const float* const* pB,
    unsigned long long (&acc)[2][JW], char* raw) {
    float (*As2)[32][66] = (float (*)[32][66])raw;
    const int BW = 32 * JW + 2;
    float* Bs = (float*)(raw + 16896);   // [2][32][BW]
    const int tid = threadIdx.x;
    const int lk = tid & 31, lr = tid >> 5;
    const int tx = tid & 15, ty = tid >> 4;
    float av[4], bv[4 * JW];
    auto ld = [&](int kc) {
#pragma unroll
        for (int i = 0; i < 4; i++) av[i] = pA[i][kc + lk];
#pragma unroll
        for (int i = 0; i < 4 * JW; i++) bv[i] = pB[i][kc + lk];
    };
    auto st = [&](int buf) {
#pragma unroll
        for (int i = 0; i < 4; i++)
            *(float2*)&As2[buf][lk][2 * (lr + 8 * i)] = make_float2(av[i], av[i]);
#pragma unroll
        for (int i = 0; i < 4 * JW; i++)
            Bs[(buf * 32 + lk) * BW + lr + 8 * i] = bv[i];
    };
    ld(0); st(0);
    __syncthreads();
    for (int c = 0; c < 16; c++) {
        const int buf = c & 1;
        if (c < 15) ld((c + 1) * 32);
#pragma unroll
        for (int kk = 0; kk < 32; kk++) {
            unsigned long long a0 =
                *(const unsigned long long*)&As2[buf][kk][ty * 4];
            unsigned long long a1 =
                *(const unsigned long long*)&As2[buf][kk][ty * 4 + 2];
#pragma unroll
            for (int p = 0; p < JW; p++) {
                unsigned long long w = *(const unsigned long long*)
                    &Bs[(buf * 32 + kk) * BW + tx * 2 * JW + 2 * p];
                FMA2(acc[0][p], a0, w);
                FMA2(acc[1][p], a1, w);
            }
        }
        if (c < 15) st(buf ^ 1);
        __syncthreads();
    }
}

// ---------------- qpre: de @ mlpW[:, :512]^T, exact round-2 k<512 order -----
__device__ void qpre_phase(const int* __restrict__ tseq,
                           const float* __restrict__ demb,
                           const float* __restrict__ mlpW, char* raw) {
    const int tid = threadIdx.x;
    const int lr = tid >> 5;
    const int tx = tid & 15, ty = tid >> 4;
    for (int tile = blockIdx.x; tile < 12800; tile += NB) {
        int rowt = tile >> 3, nt = tile & 7;
        int r0 = rowt * 32, n0 = nt * 64;
        const float* pA[4];
        const float* pB[8];
#pragma unroll
        for (int i = 0; i < 4; i++) {
            int r = r0 + lr + 8 * i;
            int t = r >> 8, b = r & 255;
            int tok = (t == 0) ? 1 : tseq[(t - 1) * BB + b];
            pA[i] = demb + (size_t)tok * HH;
        }
#pragma unroll
        for (int i = 0; i < 8; i++)
            pB[i] = mlpW + (size_t)(n0 + lr + 8 * i) * 1024;
        unsigned long long acc[2][2] = {{0ull, 0ull}, {0ull, 0ull}};
        gemm_core<2>(pA, pB, acc, raw);
#pragma unroll
        for (int r = 0; r < 2; r++) {
            int row = r0 + ty * 2 + r;
#pragma unroll
            for (int p = 0; p < 2; p++) {
                float2 v = u2f2(acc[r][p]);
                *(float2*)&g_qpre[(size_t)row * HH + n0 + tx * 4 + 2 * p] = v;
            }
        }
        __syncthreads();
    }
}

// ---------------- mlp ctx half: acc starts at qpre, continues k=512..1023 ---
__device__ void mlp_phase(int t, const float* __restrict__ mlpW,
                          const float* __restrict__ mlpb, char* raw) {
    const int tid = threadIdx.x;
    const int lr = tid >> 5;
    const int tx = tid & 15, ty = tid >> 4;
    const int bB = (blockIdx.x & 7) * 32, n0 = (blockIdx.x >> 3) * 32;
    const float* pA[4];
    const float* pB[4];
#pragma unroll
    for (int i = 0; i < 4; i++) {
        pA[i] = g_ctx + (size_t)(bB + lr + 8 * i) * HH;
        pB[i] = mlpW + (size_t)(n0 + lr + 8 * i) * 1024 + 512;
    }
    unsigned long long acc[2][1];
#pragma unroll
    for (int r = 0; r < 2; r++)
        acc[r][0] = *(const unsigned long long*)
            &g_qpre[(size_t)(t * BB + bB + ty * 2 + r) * HH + n0 + tx * 2];
    gemm_core<1>(pA, pB, acc, raw);
#pragma unroll
    for (int r = 0; r < 2; r++) {
        int b = bB + ty * 2 + r;
        float2 v = u2f2(acc[r][0]);
        int j0 = n0 + tx * 2;
        g_xv[b * HH + j0]     = tanhf(v.x + mlpb[j0]);
        g_xv[b * HH + j0 + 1] = tanhf(v.y + mlpb[j0 + 1]);
    }
}

// ---------------- fused logits(t) + ah(t+1): N=1024, full-K sequential ------
__device__ void logah_phase(const float* __restrict__ h,
                            const float* __restrict__ outW,
                            const float* __restrict__ attW,
                            const float* __restrict__ outb,
                            const float* __restrict__ attb, char* raw) {
    const int tid = threadIdx.x;
    const int lr = tid >> 5;
    const int tx = tid & 15, ty = tid >> 4;
    const int bB = (blockIdx.x & 7) * 32, n0 = (blockIdx.x >> 3) * 64;
    const float* pA[4];
    const float* pB[8];
#pragma unroll
    for (int i = 0; i < 4; i++)
        pA[i] = h + (size_t)(bB + lr + 8 * i) * HH;
#pragma unroll
    for (int i = 0; i < 8; i++) {
        int n = n0 + lr + 8 * i;
        pB[i] = (n < 512) ? outW + (size_t)n * HH : attW + (size_t)(n - 512) * HH;
    }
    unsigned long long acc[2][2] = {{0ull, 0ull}, {0ull, 0ull}};
    gemm_core<2>(pA, pB, acc, raw);
#pragma unroll
    for (int r = 0; r < 2; r++) {
        int b = bB + ty * 2 + r;
#pragma unroll
        for (int p = 0; p < 2; p++) {
            float2 v = u2f2(acc[r][p]);
#pragma unroll
            for (int l = 0; l < 2; l++) {
                int n = n0 + tx * 4 + 2 * p + l;
                float val = l ? v.y : v.x;
                if (n < 512)
                    g_logits[b * VV + n] = val + outb[n];
                else
                    g_ah[b * HH + n - 512] = fmaxf(val + attb[n - 512], 0.f);
            }
        }
    }
}

// ---------------- attention (verbatim round 2) ----------------
__device__ void attn_one(int b, char* raw) {
    float* ah   = (float*)raw;
    float* wm   = ah + 512;
    float* wsum = wm + 8;
    float* wctx = wsum + 8;

    const int tid = threadIdx.x, warp = tid >> 5, lane = tid & 31;
    ah[tid]       = g_ah[b * HH + tid];
    ah[tid + 256] = g_ah[b * HH + tid + 256];
    __syncthreads();

    float ahr[16];
#pragma unroll
    for (int i = 0; i < 16; i++) ahr[i] = ah[lane + 32 * i];

    float m = -1e30f, s = 0.f;
    float ctx[16];
#pragma unroll
    for (int i = 0; i < 16; i++) ctx[i] = 0.f;

    for (int sI = warp; sI < SB; sI += 8) {
        const float* eo = g_eo + ((size_t)sI * BB + b) * HH;
        float ev[16], d = 0.f;
#pragma unroll
        for (int i = 0; i < 16; i++) { ev[i] = eo[lane + 32 * i]; d += ev[i] * ahr[i]; }
#pragma unroll
        for (int o = 16; o > 0; o >>= 1) d += __shfl_xor_sync(0xffffffffu, d, o);
        float mn = fmaxf(m, d);
        float sc = expf(m - mn);
        float p  = expf(d - mn);
        s = s * sc + p;
#pragma unroll
        for (int i = 0; i < 16; i++) ctx[i] = ctx[i] * sc + p * ev[i];
        m = mn;
    }
    if (lane == 0) { wm[warp] = m; wsum[warp] = s; }
#pragma unroll
    for (int i = 0; i < 16; i++) wctx[warp * 512 + lane + 32 * i] = ctx[i];
    __syncthreads();

    float M = -1e30f;
#pragma unroll
    for (int w = 0; w < 8; w++) M = fmaxf(M, wm[w]);
    float S = 0.f, esc[8];
#pragma unroll
    for (int w = 0; w < 8; w++) { esc[w] = expf(wm[w] - M); S += wsum[w] * esc[w]; }
    float inv = 1.f / S;
#pragma unroll
    for (int hh = 0; hh < 2; hh++) {
        int h = tid + hh * 256;
        float acc = 0.f;
#pragma unroll
        for (int w = 0; w < 8; w++) acc += esc[w] * wctx[w * 512 + h];
        g_ctx[b * HH + h] = acc * inv;
    }
    __syncthreads();
}

// ---------------- output softmax/argmax/loss (verbatim round 2) -------------
__device__ void out_one(int t, int b, const int* __restrict__ tseq,
                        float* __restrict__ dout, char* raw) {
    float* sv = (float*)raw;
    int*   si = (int*)(raw + 1024);
    const int tid = threadIdx.x;
    const float* lrow = g_logits + b * VV;
    float v0 = lrow[tid], v1 = lrow[tid + 256];
    float mv; int mi;
    if (v0 >= v1) { mv = v0; mi = tid; } else { mv = v1; mi = tid + 256; }
    sv[tid] = mv; si[tid] = mi;
    __syncthreads();
    for (int o = 128; o > 0; o >>= 1) {
        if (tid < o) {
            float ov = sv[tid + o]; int oi = si[tid + o];
            if (ov > sv[tid] || (ov == sv[tid] && oi < si[tid])) { sv[tid] = ov; si[tid] = oi; }
        }
        __syncthreads();
    }
    float bmax = sv[0];
    int pred = si[0];
    __syncthreads();
    sv[tid] = expf(v0 - bmax) + expf(v1 - bmax);
    __syncthreads();
    for (int o = 128; o > 0; o >>= 1) {
        if (tid < o) sv[tid] += sv[tid + o];
        __syncthreads();
    }
    if (tid == 0) {
        int tgt = tseq[t * BB + b];
        float p = expf(lrow[tgt] - bmax) / sv[0];
        p = fmaxf(p, 1e-10f);
        g_loss_tb[t * BB + b] = -logf(p);
        dout[t * BB + b] = (float)pred;
    }
    __syncthreads();
}

// ---------------- persistent mega-kernel ----------------
__global__ void __launch_bounds__(NT) k_mega(
    const int* __restrict__ iseq, const int* __restrict__ ilen,
    const int* __restrict__ tseq,
    const float* __restrict__ eemb,
    const float* __restrict__ eWih, const float* __restrict__ eWhh,
    const float* __restrict__ ebih, const float* __restrict__ ebhh,
    const float* __restrict__ attW, const float* __restrict__ attb,
    const float* __restrict__ demb,
    const float* __restrict__ dWih, const float* __restrict__ dWhh,
    const float* __restrict__ dbih, const float* __restrict__ dbhh,
    const float* __restrict__ mlpW, const float* __restrict__ mlpb,
    const float* __restrict__ outW, const float* __restrict__ outb,
    float* __restrict__ dout) {

    __shared__ __align__(16) char raw[SMEM_BYTES];
    const int bid = blockIdx.x, tid = threadIdx.x;

    for (int i = bid * NT + tid; i < BB * HH; i += NB * NT) g_h[0][i] = 0.f;
    gsync();

    qpre_phase(tseq, demb, mlpW, raw);
    gsync();

    // encoder
    for (int s = 0; s < SB; s++) {
        int pin = s & 1;
        gru_step<true>(s, iseq, eemb, nullptr, g_h[pin], g_h[pin ^ 1],
                       g_eo + (size_t)s * BB * HH,
                       eWih, eWhh, ebih, ebhh, ilen, raw);
        gsync();
    }

    // ah for t=0 (logits half is junk, never read)
    logah_phase(g_h[0], outW, attW, outb, attb, raw);
    gsync();

    // decoder: 4 barriers/step
    for (int t = 0; t < TB; t++) {
        int pin = t & 1;
        if (t > 0) {
            out_one(t - 1, bid * 2 + 0, tseq, dout, raw);
            out_one(t - 1, bid * 2 + 1, tseq, dout, raw);
        }
        attn_one(bid * 2 + 0, raw);
        attn_one(bid * 2 + 1, raw);
        gsync();
        mlp_phase(t, mlpW, mlpb, raw);
        gsync();
        gru_step<false>(0, nullptr, nullptr, g_xv, g_h[pin], g_h[pin ^ 1],
                        nullptr, dWih, dWhh, dbih, dbhh, nullptr, raw);
        gsync();
        logah_phase(g_h[pin ^ 1], outW, attW, outb, attb, raw);
        gsync();
    }
    out_one(TB - 1, bid * 2 + 0, tseq, dout, raw);
    out_one(TB - 1, bid * 2 + 1, tseq, dout, raw);
    gsync();

    if (bid != 0) return;
    {
        float* sf = (float*)raw;
        int*   sc = (int*)(raw + 1024);
        int*   sa = (int*)(raw + 2048);
        float ls = 0.f; int corr = 0;
        for (int i = tid; i < TB * BB; i += NT) {
            ls += g_loss_tb[i];
            corr += (dout[i] == (float)tseq[i]) ? 1 : 0;
        }
        int allc = 1;
        for (int t = 0; t < TB; t++)
            if (dout[t * BB + tid] != (float)tseq[t * BB + tid]) { allc = 0; break; }
        sf[tid] = ls; sc[tid] = corr; sa[tid] = allc;
        __syncthreads();
        for (int o = 128; o > 0; o >>= 1) {
            if (tid < o) { sf[tid] += sf[tid + o]; sc[tid] += sc[tid + o]; sa[tid] += sa[tid + o]; }
            __syncthreads();
        }
        if (tid == 0) {
            dout[TB * BB]     = sf[0] / (float)(TB * BB);
            dout[TB * BB + 1] = (float)sa[0] / (float)BB;
            dout[TB * BB + 2] = (float)sc[0] / (float)(TB * BB);
        }
    }
}

// ---------------- host ----------------
extern "C" void kernel_launch(void* const* d_in, const int* in_sizes, int n_in,
                              void* d_out, int out_size) {
    (void)in_sizes; (void)n_in; (void)out_size;
    k_mega<<<NB, NT>>>(
        (const int*)d_in[0], (const int*)d_in[1], (const int*)d_in[2],
        (const float*)d_in[3], (const float*)d_in[4], (const float*)d_in[5],
        (const float*)d_in[6], (const float*)d_in[7], (const float*)d_in[8],
        (const float*)d_in[9], (const float*)d_in[10], (const float*)d_in[11],
        (const float*)d_in[12], (const float*)d_in[13], (const float*)d_in[14],
        (const float*)d_in[15], (const float*)d_in[16], (const float*)d_in[17],
        (const float*)d_in[18], (float*)d_out);
}